// round 5
// baseline (speedup 1.0000x reference)
#include <cuda_runtime.h>
#include <math.h>

#define NN 100000
#define MPAD 100096          // 128 * 782
#define NE 600000
#define NG 64
#define D 128
#define G3 384

// ---------------- scratch (device globals; no allocation) ----------------
__device__ float g_x0[MPAD * D];
__device__ float g_x1[MPAD * D];
__device__ float g_S[MPAD * G3];
__device__ float g_cnt[MPAD * 4];
__device__ float g_Wc[384 * 128];     // msg_W reshaped (t,i)->k, transposed
__device__ float g_Wcomb[384 * 384];  // Wc @ W_ih^T (fp32)
__device__ float g_Wbig[512 * 512];   // combined weights, col-permuted, tf32-rounded
__device__ float g_bbase[512];        // col-permuted
__device__ float g_mb3[3 * 512];      // col-permuted
__device__ int   g_hist[NN];
__device__ int   g_off[NN + 1];
__device__ int   g_curp[NN];
__device__ int   g_tmp[NN];
__device__ int   g_bsum[128];
__device__ int   g_entries[NE];       // src | (type<<20), grouped by dst
__device__ float g_pool[NG * D];
__device__ float g_pcnt[NG];

// ---------------- helpers ----------------
__device__ __forceinline__ float tf32r(float x) {
    unsigned u;
    asm("cvt.rna.tf32.f32 %0, %1;" : "=r"(u) : "f"(x));
    return __uint_as_float(u);
}

__device__ __forceinline__ void mma_tf32(float c[4], const unsigned a[4],
                                         unsigned b0, unsigned b1) {
    asm volatile(
        "mma.sync.aligned.m16n8k8.row.col.f32.tf32.tf32.f32 "
        "{%0,%1,%2,%3}, {%4,%5,%6,%7}, {%8,%9}, {%0,%1,%2,%3};"
        : "+f"(c[0]), "+f"(c[1]), "+f"(c[2]), "+f"(c[3])
        : "r"(a[0]), "r"(a[1]), "r"(a[2]), "r"(a[3]), "r"(b0), "r"(b1));
}

__device__ __forceinline__ float sigm(float v) { return 1.f / (1.f + expf(-v)); }

// column permutation: original col c = t*128 + j  (t=gate, j=output dim)
// newcol nc = (j>>4)*64 + t*16 + (j&15)
// inverse: t = (nc>>4)&3 ; j = ((nc>>6)<<4) | (nc&15)

// ---------------- preprocessing ----------------
__global__ void k_prep_wc(const float* __restrict__ msgW) {
    int i = blockIdx.x * 256 + threadIdx.x;
    if (i < 384 * 128) {
        int k = i >> 7, o = i & 127;
        g_Wc[i] = msgW[(k >> 7) * D * D + o * D + (k & 127)];
    }
}

__global__ void k_prep_comb(const float* __restrict__ Wih) {
    int i = blockIdx.x * 256 + threadIdx.x;
    if (i >= 384 * 384) return;
    int k = i / 384, o = i % 384;
    float acc = 0.f;
#pragma unroll 8
    for (int j = 0; j < 128; j++) acc += g_Wc[k * 128 + j] * Wih[o * 128 + j];
    g_Wcomb[i] = acc;
}

__global__ void k_prep_big(const float* __restrict__ Whh) {
    int i = blockIdx.x * 256 + threadIdx.x;
    if (i >= 512 * 512) return;
    int k = i >> 9, nc = i & 511;
    int t = (nc >> 4) & 3;
    int j = ((nc >> 6) << 4) | (nc & 15);
    int c = t * 128 + j;
    float v;
    if (c < 256)      v = (k < 384) ? g_Wcomb[k * 384 + c] : Whh[c * 128 + (k - 384)];
    else if (c < 384) v = (k < 384) ? g_Wcomb[k * 384 + c] : 0.f;
    else              v = (k >= 384) ? Whh[(c - 128) * 128 + (k - 384)] : 0.f;
    g_Wbig[k * 512 + nc] = tf32r(v);
}

__global__ void k_prep_bias(const float* __restrict__ bih, const float* __restrict__ bhh,
                            const float* __restrict__ msgb, const float* __restrict__ Wih) {
    int i = blockIdx.x * 256 + threadIdx.x;
    if (i < 512) {
        int nc = i;
        int t = (nc >> 4) & 3;
        int j = ((nc >> 6) << 4) | (nc & 15);
        int c = t * 128 + j;
        g_bbase[nc] = (c < 256) ? bih[c] + bhh[c] : (c < 384 ? bih[c] : bhh[c - 128]);
    }
    if (i >= 512 && i < 512 + 3 * 512) {
        int jj = i - 512;
        int tp = jj >> 9, nc = jj & 511;
        int t = (nc >> 4) & 3;
        int j = ((nc >> 6) << 4) | (nc & 15);
        int c = t * 128 + j;
        float v = 0.f;
        if (c < 384) {
#pragma unroll 8
            for (int k = 0; k < 128; k++) v += msgb[tp * 128 + k] * Wih[c * 128 + k];
        }
        g_mb3[tp * 512 + nc] = v;
    }
}

__global__ void k_init(const int* __restrict__ xt, const int* __restrict__ xk,
                       const float* __restrict__ xs,
                       const float* __restrict__ temb,
                       const float* __restrict__ kemb) {
    int idx = blockIdx.x * 256 + threadIdx.x;
    if (idx >= NN * D) return;
    int n = idx >> 7, d = idx & 127;
    float v;
    if (d < 32)       v = temb[xt[n] * 32 + d];
    else if (d < 64)  v = kemb[xk[n] * 32 + (d - 32)];
    else              v = xs[n * 64 + (d - 64)];
    g_x0[idx] = v;
}

__global__ void k_zero_hist() {
    int i = blockIdx.x * 256 + threadIdx.x;
    if (i < NN) g_hist[i] = 0;
}

__global__ void k_hist(const int* __restrict__ dst, int E) {
    int e = blockIdx.x * 256 + threadIdx.x;
    if (e < E) atomicAdd(&g_hist[dst[e]], 1);
}

__global__ void k_scan1() {
    __shared__ int s[1024];
    int i = blockIdx.x * 1024 + threadIdx.x;
    s[threadIdx.x] = (i < NN) ? g_hist[i] : 0;
    __syncthreads();
    for (int off = 1; off < 1024; off <<= 1) {
        int t = 0;
        if (threadIdx.x >= off) t = s[threadIdx.x - off];
        __syncthreads();
        if (threadIdx.x >= off) s[threadIdx.x] += t;
        __syncthreads();
    }
    if (i < NN) g_tmp[i] = s[threadIdx.x];
    if (threadIdx.x == 1023) g_bsum[blockIdx.x] = s[1023];
}

__global__ void k_scan2(int nb) {
    int acc = 0;
    for (int b = 0; b < nb; b++) { acc += g_bsum[b]; g_bsum[b] = acc; }
}

__global__ void k_scan3() {
    int i = blockIdx.x * 1024 + threadIdx.x;
    if (i < NN) {
        int add = blockIdx.x ? g_bsum[blockIdx.x - 1] : 0;
        g_off[i + 1] = g_tmp[i] + add;
    }
    if (i == 0) g_off[0] = 0;
}

__global__ void k_copycur() {
    int i = blockIdx.x * 256 + threadIdx.x;
    if (i < NN) g_curp[i] = g_off[i];
}

__global__ void k_scatter(const int* __restrict__ src, const int* __restrict__ dst,
                          const int* __restrict__ et, int E) {
    int e = blockIdx.x * 256 + threadIdx.x;
    if (e >= E) return;
    int dd = dst[e];
    int pos = atomicAdd(&g_curp[dd], 1);
    g_entries[pos] = src[e] | (et[e] << 20);
}

// ---------------- gather: S[n, t*128+:] = sum x[src], high occupancy ----------------
__device__ __forceinline__ void f4add(float4& a, const float4& b) {
    a.x += b.x; a.y += b.y; a.z += b.z; a.w += b.w;
}

__global__ void k_gather(const float* __restrict__ x) {
    int n = blockIdx.x * 8 + (threadIdx.x >> 5);
    if (n >= NN) return;
    int lane = threadIdx.x & 31;
    float4 a0 = make_float4(0.f, 0.f, 0.f, 0.f), a1 = a0, a2 = a0;
    int c0 = 0, c1 = 0, c2 = 0;
    int beg = g_off[n], end = g_off[n + 1];
    for (int j = beg; j < end; ++j) {
        int e = g_entries[j];
        int s = e & 0xFFFFF, t = e >> 20;
        float4 v = ((const float4*)(x + (size_t)s * D))[lane];
        if (t == 0)      { f4add(a0, v); c0++; }
        else if (t == 1) { f4add(a1, v); c1++; }
        else             { f4add(a2, v); c2++; }
    }
    float4* Sp = (float4*)(g_S + (size_t)n * G3);
    Sp[lane] = a0; Sp[32 + lane] = a1; Sp[64 + lane] = a2;
    if (lane == 0) {
        g_cnt[n * 4 + 0] = (float)c0;
        g_cnt[n * 4 + 1] = (float)c1;
        g_cnt[n * 4 + 2] = (float)c2;
    }
}

// ---------------- one GEMM + register-local GRU epilogue ----------------
// C[m, nc] = [S|x][m, :512] @ Wbig[:, nc]; gates of output dim j live in the
// same thread's fragments (nt = gate*2 + h) thanks to the column permutation.
__global__ void __launch_bounds__(256)
k_big(const float* __restrict__ x, float* __restrict__ xn) {
    __shared__ float As[2][128][20];
    __shared__ float Bs[2][16][136];
    __shared__ float sb[4][128];

    const int tid  = threadIdx.x;
    const int wid  = tid >> 5, lane = tid & 31;
    const int gid  = lane >> 2, tig = lane & 3;
    const int wm   = (wid >> 1) * 32;
    const int wn   = (wid & 1) * 64;
    const int nb   = blockIdx.x;          // 0..3 (col block; fastest for L2 A reuse)
    const int bm   = blockIdx.y * 128;

    const int ar = tid >> 1, ac = (tid & 1) * 8;
    const int br = tid >> 4, bc = (tid & 15) * 4;

    const float* srcS = g_S + (size_t)(bm + ar) * G3;
    const float* srcX = x + (size_t)(bm + ar) * D;

    if (tid < 128) {
        sb[0][tid] = g_bbase[nb * 128 + tid];
        sb[1][tid] = g_mb3[nb * 128 + tid];
        sb[2][tid] = g_mb3[512 + nb * 128 + tid];
        sb[3][tid] = g_mb3[1024 + nb * 128 + tid];
    }

    float acc[2][8][4];
#pragma unroll
    for (int a = 0; a < 2; a++)
#pragma unroll
        for (int b = 0; b < 8; b++)
#pragma unroll
            for (int q = 0; q < 4; q++) acc[a][b][q] = 0.f;

#define LOAD_A(BUF, K0)                                                        \
    _Pragma("unroll")                                                          \
    for (int i = 0; i < 2; i++) {                                              \
        int kk = (K0) + ac + i * 4;                                            \
        float4 v = (kk < 384) ? *(const float4*)(srcS + kk)                    \
                              : *(const float4*)(srcX + kk - 384);             \
        float* p = &As[BUF][ar][ac + i * 4];                                   \
        p[0] = tf32r(v.x); p[1] = tf32r(v.y); p[2] = tf32r(v.z); p[3] = tf32r(v.w); \
    }
#define LOAD_B(BUF, K0)                                                        \
    _Pragma("unroll")                                                          \
    for (int i = 0; i < 2; i++) {                                              \
        *(float4*)&Bs[BUF][br][bc + i * 64] =                                  \
            *(const float4*)(g_Wbig + (size_t)((K0) + br) * 512 + nb * 128 + bc + i * 64); \
    }

    LOAD_A(0, 0)
    LOAD_B(0, 0)
    __syncthreads();

    const int NC = 32;
    for (int c = 0; c < NC; c++) {
        int buf = c & 1;
        if (c + 1 < NC) {
            LOAD_A(buf ^ 1, (c + 1) * 16)
            LOAD_B(buf ^ 1, (c + 1) * 16)
        }
#pragma unroll
        for (int kk = 0; kk < 16; kk += 8) {
            unsigned a[2][4];
#pragma unroll
            for (int mt = 0; mt < 2; mt++) {
                int m = wm + mt * 16;
                a[mt][0] = __float_as_uint(As[buf][m + gid][kk + tig]);
                a[mt][1] = __float_as_uint(As[buf][m + gid + 8][kk + tig]);
                a[mt][2] = __float_as_uint(As[buf][m + gid][kk + tig + 4]);
                a[mt][3] = __float_as_uint(As[buf][m + gid + 8][kk + tig + 4]);
            }
#pragma unroll
            for (int nt = 0; nt < 8; nt++) {
                unsigned b0 = __float_as_uint(Bs[buf][kk + tig][wn + nt * 8 + gid]);
                unsigned b1 = __float_as_uint(Bs[buf][kk + tig + 4][wn + nt * 8 + gid]);
                mma_tf32(acc[0][nt], a[0], b0, b1);
                mma_tf32(acc[1][nt], a[1], b0, b1);
            }
        }
        __syncthreads();
    }

    // GRU epilogue, fully register-local per output element
    const int h64 = wn >> 6;   // 0 or 1
#pragma unroll
    for (int mt = 0; mt < 2; mt++) {
#pragma unroll
        for (int rsel = 0; rsel < 2; rsel++) {
            int row = bm + wm + mt * 16 + gid + rsel * 8;
            float c0 = g_cnt[row * 4], c1 = g_cnt[row * 4 + 1], c2 = g_cnt[row * 4 + 2];
#pragma unroll
            for (int h = 0; h < 2; h++) {
                int jbase = nb * 32 + h64 * 16 + h * 8 + tig * 2;
                float2 o;
#pragma unroll
                for (int p = 0; p < 2; p++) {
                    int lc = (wn & 63) + h * 8 + tig * 2 + p;  // gate-0 col within 64-grp
                    int lR = wn + lc - (wn & 63);              // = wn + h*8+tig*2+p
                    int q = rsel * 2 + p;
                    lR = wn + h * 8 + tig * 2 + p;
                    int lZ = lR + 16, lN = lR + 32, lH = lR + 48;
                    float vR = acc[mt][0 + h][q] + sb[0][lR]
                             + c0 * sb[1][lR] + c1 * sb[2][lR] + c2 * sb[3][lR];
                    float vZ = acc[mt][2 + h][q] + sb[0][lZ]
                             + c0 * sb[1][lZ] + c1 * sb[2][lZ] + c2 * sb[3][lZ];
                    float vN = acc[mt][4 + h][q] + sb[0][lN]
                             + c0 * sb[1][lN] + c1 * sb[2][lN] + c2 * sb[3][lN];
                    float vH = acc[mt][6 + h][q] + sb[0][lH];  // mb3 is 0 for h_n cols
                    float rg = sigm(vR), zg = sigm(vZ);
                    float ng = tanhf(vN + rg * vH);
                    float hp = x[(size_t)row * D + jbase + p];
                    (&o.x)[p] = (1.f - zg) * ng + zg * hp;
                }
                *(float2*)(xn + (size_t)row * D + jbase) = o;
            }
        }
    }
#undef LOAD_A
#undef LOAD_B
}

// ---------------- readout ----------------
__global__ void k_zero_pool() {
    int i = blockIdx.x * 256 + threadIdx.x;
    if (i < NG * D) g_pool[i] = 0.f;
    if (i < NG) g_pcnt[i] = 0.f;
}

__global__ void k_pool(const float* __restrict__ x, const int* __restrict__ batch) {
    int idx = blockIdx.x * 256 + threadIdx.x;
    if (idx >= NN * D) return;
    int n = idx >> 7, d = idx & 127;
    int g = batch[n];
    atomicAdd(&g_pool[g * D + d], x[idx]);
    if (d == 0) atomicAdd(&g_pcnt[g], 1.f);
}

__global__ void k_mlp(const float* __restrict__ W1, const float* __restrict__ b1,
                      const float* __restrict__ W2, const float* __restrict__ b2,
                      float* __restrict__ out) {
    int g = blockIdx.x;
    int d = threadIdx.x;
    __shared__ float ps[128];
    __shared__ float red[4];
    float c = g_pcnt[g]; if (c < 1.f) c = 1.f;
    ps[d] = g_pool[g * D + d] / c;
    __syncthreads();
    float acc = b1[d];
#pragma unroll
    for (int k = 0; k < 128; k++) acc += ps[k] * W1[d * 128 + k];
    float h = acc > 0.f ? acc : 0.f;
    float v = h * W2[d];
#pragma unroll
    for (int off = 16; off; off >>= 1) v += __shfl_down_sync(0xffffffff, v, off);
    if ((d & 31) == 0) red[d >> 5] = v;
    __syncthreads();
    if (d == 0) out[g] = red[0] + red[1] + red[2] + red[3] + b2[0];
}

// ---------------- launch ----------------
extern "C" void kernel_launch(void* const* d_in, const int* in_sizes, int n_in,
                              void* d_out, int out_size) {
    const int*   x_type   = (const int*)d_in[0];
    const int*   x_tok    = (const int*)d_in[1];
    const float* x_small  = (const float*)d_in[2];
    const int*   ei       = (const int*)d_in[3];
    const int*   etype    = (const int*)d_in[4];
    const int*   batch    = (const int*)d_in[5];
    const float* type_emb = (const float*)d_in[6];
    const float* tok_emb  = (const float*)d_in[7];
    const float* msg_W    = (const float*)d_in[8];
    const float* msg_b    = (const float*)d_in[9];
    const float* W_ih     = (const float*)d_in[10];
    const float* W_hh     = (const float*)d_in[11];
    const float* b_ih     = (const float*)d_in[12];
    const float* b_hh     = (const float*)d_in[13];
    const float* pW1      = (const float*)d_in[14];
    const float* pb1      = (const float*)d_in[15];
    const float* pW2      = (const float*)d_in[16];
    const float* pb2      = (const float*)d_in[17];

    const int E = NE;
    const int* src = ei;
    const int* dst = ei + E;

    float *pX0, *pX1;
    cudaGetSymbolAddress((void**)&pX0, g_x0);
    cudaGetSymbolAddress((void**)&pX1, g_x1);

    // preprocessing
    k_prep_wc<<<(384 * 128 + 255) / 256, 256>>>(msg_W);
    k_prep_comb<<<(384 * 384 + 255) / 256, 256>>>(W_ih);
    k_prep_big<<<(512 * 512 + 255) / 256, 256>>>(W_hh);
    k_prep_bias<<<(2048 + 255) / 256, 256>>>(b_ih, b_hh, msg_b, W_ih);
    k_init<<<(NN * D + 255) / 256, 256>>>(x_type, x_tok, x_small, type_emb, tok_emb);
    k_zero_hist<<<(NN + 255) / 256, 256>>>();
    k_hist<<<(E + 255) / 256, 256>>>(dst, E);
    k_scan1<<<98, 1024>>>();
    k_scan2<<<1, 1>>>(98);
    k_scan3<<<98, 1024>>>();
    k_copycur<<<(NN + 255) / 256, 256>>>();
    k_scatter<<<(E + 255) / 256, 256>>>(src, dst, etype, E);

    float* cur = pX0;
    float* nxt = pX1;
    dim3 gBig(4, MPAD / 128);
    for (int it = 0; it < 8; it++) {
        k_gather<<<(NN + 7) / 8, 256>>>(cur);
        k_big<<<gBig, 256>>>(cur, nxt);
        float* t = cur; cur = nxt; nxt = t;
    }

    k_zero_pool<<<33, 256>>>();
    k_pool<<<(NN * D + 255) / 256, 256>>>(cur, batch);
    k_mlp<<<NG, 128>>>(pW1, pb1, pW2, pb2, (float*)d_out);
}

// round 7
// speedup vs baseline: 1.2075x; 1.2075x over previous
#include <cuda_runtime.h>
#include <cuda_fp16.h>
#include <math.h>
#include <stdint.h>

#define NN 100000
#define MPAD 100096          // 128 * 782
#define NE 600000
#define NG 64
#define D 128
#define G3 384

// ---------------- scratch (device globals; no allocation) ----------------
__device__ float g_x0[MPAD * D];
__device__ float g_x1[MPAD * D];
__device__ float g_S[MPAD * G3];
__device__ float g_cnt[MPAD * 4];
__device__ float g_Wc[384 * 128];     // msg_W reshaped (t,i)->k, transposed
__device__ float g_Wcomb[384 * 384];  // Wc @ W_ih^T (fp32)
__device__ __half g_Wh[512 * 512];    // combined weights, col-permuted, [n][k] fp16
__device__ float g_bbase[512];        // col-permuted
__device__ float g_mb3[3 * 512];      // col-permuted
__device__ int   g_hist[NN];
__device__ int   g_off[NN + 1];
__device__ int   g_curp[NN];
__device__ int   g_tmp[NN];
__device__ int   g_bsum[128];
__device__ int   g_entries[NE];       // src | (type<<20), grouped by dst
__device__ float g_pool[NG * D];
__device__ float g_pcnt[NG];

// ---------------- helpers ----------------
__device__ __forceinline__ float sigm(float v) { return 1.f / (1.f + expf(-v)); }

__device__ __forceinline__ void mma_f16(float c[4], const unsigned a[4],
                                        unsigned b0, unsigned b1) {
    asm volatile(
        "mma.sync.aligned.m16n8k16.row.col.f32.f16.f16.f32 "
        "{%0,%1,%2,%3}, {%4,%5,%6,%7}, {%8,%9}, {%0,%1,%2,%3};"
        : "+f"(c[0]), "+f"(c[1]), "+f"(c[2]), "+f"(c[3])
        : "r"(a[0]), "r"(a[1]), "r"(a[2]), "r"(a[3]), "r"(b0), "r"(b1));
}

// column permutation: original col c = t*128 + j  (t=gate, j=output dim)
// newcol nc = (j>>4)*64 + t*16 + (j&15)
// inverse: t = (nc>>4)&3 ; j = ((nc>>6)<<4) | (nc&15)

// ---------------- preprocessing ----------------
__global__ void k_prep_wc(const float* __restrict__ msgW) {
    int i = blockIdx.x * 256 + threadIdx.x;
    if (i < 384 * 128) {
        int k = i >> 7, o = i & 127;
        g_Wc[i] = msgW[(k >> 7) * D * D + o * D + (k & 127)];
    }
}

__global__ void k_prep_comb(const float* __restrict__ Wih) {
    int i = blockIdx.x * 256 + threadIdx.x;
    if (i >= 384 * 384) return;
    int k = i / 384, o = i % 384;
    float acc = 0.f;
#pragma unroll 8
    for (int j = 0; j < 128; j++) acc += g_Wc[k * 128 + j] * Wih[o * 128 + j];
    g_Wcomb[i] = acc;
}

// g_Wh[n][k] = Wbig_perm[k][n] in fp16 (k contiguous)
__global__ void k_prep_wh(const float* __restrict__ Whh) {
    int i = blockIdx.x * 256 + threadIdx.x;
    if (i >= 512 * 512) return;
    int n = i >> 9, k = i & 511;
    int t = (n >> 4) & 3;
    int j = ((n >> 6) << 4) | (n & 15);
    int col = t * 128 + j;
    float v;
    if (col < 256)      v = (k < 384) ? g_Wcomb[k * 384 + col] : Whh[col * 128 + (k - 384)];
    else if (col < 384) v = (k < 384) ? g_Wcomb[k * 384 + col] : 0.f;
    else                v = (k >= 384) ? Whh[(col - 128) * 128 + (k - 384)] : 0.f;
    g_Wh[(size_t)n * 512 + k] = __float2half_rn(v);
}

__global__ void k_prep_bias(const float* __restrict__ bih, const float* __restrict__ bhh,
                            const float* __restrict__ msgb, const float* __restrict__ Wih) {
    int i = blockIdx.x * 256 + threadIdx.x;
    if (i < 512) {
        int nc = i;
        int t = (nc >> 4) & 3;
        int j = ((nc >> 6) << 4) | (nc & 15);
        int c = t * 128 + j;
        g_bbase[nc] = (c < 256) ? bih[c] + bhh[c] : (c < 384 ? bih[c] : bhh[c - 128]);
    }
    if (i >= 512 && i < 512 + 3 * 512) {
        int jj = i - 512;
        int tp = jj >> 9, nc = jj & 511;
        int t = (nc >> 4) & 3;
        int j = ((nc >> 6) << 4) | (nc & 15);
        int c = t * 128 + j;
        float v = 0.f;
        if (c < 384) {
#pragma unroll 8
            for (int k = 0; k < 128; k++) v += msgb[tp * 128 + k] * Wih[c * 128 + k];
        }
        g_mb3[tp * 512 + nc] = v;
    }
}

__global__ void k_init(const int* __restrict__ xt, const int* __restrict__ xk,
                       const float* __restrict__ xs,
                       const float* __restrict__ temb,
                       const float* __restrict__ kemb) {
    int idx = blockIdx.x * 256 + threadIdx.x;
    if (idx >= NN * D) return;
    int n = idx >> 7, d = idx & 127;
    float v;
    if (d < 32)       v = temb[xt[n] * 32 + d];
    else if (d < 64)  v = kemb[xk[n] * 32 + (d - 32)];
    else              v = xs[n * 64 + (d - 64)];
    g_x0[idx] = v;
}

__global__ void k_zero_hist() {
    int i = blockIdx.x * 256 + threadIdx.x;
    if (i < NN) g_hist[i] = 0;
}

__global__ void k_hist(const int* __restrict__ dst, int E) {
    int e = blockIdx.x * 256 + threadIdx.x;
    if (e < E) atomicAdd(&g_hist[dst[e]], 1);
}

__global__ void k_scan1() {
    __shared__ int s[1024];
    int i = blockIdx.x * 1024 + threadIdx.x;
    s[threadIdx.x] = (i < NN) ? g_hist[i] : 0;
    __syncthreads();
    for (int off = 1; off < 1024; off <<= 1) {
        int t = 0;
        if (threadIdx.x >= off) t = s[threadIdx.x - off];
        __syncthreads();
        if (threadIdx.x >= off) s[threadIdx.x] += t;
        __syncthreads();
    }
    if (i < NN) g_tmp[i] = s[threadIdx.x];
    if (threadIdx.x == 1023) g_bsum[blockIdx.x] = s[1023];
}

__global__ void k_scan2(int nb) {
    int acc = 0;
    for (int b = 0; b < nb; b++) { acc += g_bsum[b]; g_bsum[b] = acc; }
}

__global__ void k_scan3() {
    int i = blockIdx.x * 1024 + threadIdx.x;
    if (i < NN) {
        int add = blockIdx.x ? g_bsum[blockIdx.x - 1] : 0;
        g_off[i + 1] = g_tmp[i] + add;
    }
    if (i == 0) g_off[0] = 0;
}

__global__ void k_copycur() {
    int i = blockIdx.x * 256 + threadIdx.x;
    if (i < NN) g_curp[i] = g_off[i];
}

__global__ void k_scatter(const int* __restrict__ src, const int* __restrict__ dst,
                          const int* __restrict__ et, int E) {
    int e = blockIdx.x * 256 + threadIdx.x;
    if (e >= E) return;
    int dd = dst[e];
    int pos = atomicAdd(&g_curp[dd], 1);
    g_entries[pos] = src[e] | (et[e] << 20);
}

// ---------------- gather ----------------
__device__ __forceinline__ void f4add(float4& a, const float4& b) {
    a.x += b.x; a.y += b.y; a.z += b.z; a.w += b.w;
}

__global__ void k_gather(const float* __restrict__ x) {
    int n = blockIdx.x * 8 + (threadIdx.x >> 5);
    if (n >= NN) return;
    int lane = threadIdx.x & 31;
    float4 a0 = make_float4(0.f, 0.f, 0.f, 0.f), a1 = a0, a2 = a0;
    int c0 = 0, c1 = 0, c2 = 0;
    int beg = g_off[n], end = g_off[n + 1];
    for (int j = beg; j < end; ++j) {
        int e = g_entries[j];
        int s = e & 0xFFFFF, t = e >> 20;
        float4 v = ((const float4*)(x + (size_t)s * D))[lane];
        if (t == 0)      { f4add(a0, v); c0++; }
        else if (t == 1) { f4add(a1, v); c1++; }
        else             { f4add(a2, v); c2++; }
    }
    float4* Sp = (float4*)(g_S + (size_t)n * G3);
    Sp[lane] = a0; Sp[32 + lane] = a1; Sp[64 + lane] = a2;
    if (lane == 0) {
        g_cnt[n * 4 + 0] = (float)c0;
        g_cnt[n * 4 + 1] = (float)c1;
        g_cnt[n * 4 + 2] = (float)c2;
    }
}

// ---------------- fp16 fused GEMM + register-local GRU ----------------
// C[m, nc] = [S|x][m, :512] @ Wbig_perm[:, nc]; gates of output dim j live in
// one thread's fragments (nt = gate*2 + h). A: 128x32 fp16/chunk, stride 40
// halves (20 words) -> conflict-free fragment loads. B pre-fp16 [n][k].
#define ASTR 40  // halves per A/B smem row

__global__ void __launch_bounds__(256)
k_big(const float* __restrict__ x, float* __restrict__ xn) {
    __shared__ __half As[2][128 * ASTR];
    __shared__ __half Bs[2][128 * ASTR];
    __shared__ float sb[4][128];

    const int tid  = threadIdx.x;
    const int wid  = tid >> 5, lane = tid & 31;
    const int gid  = lane >> 2, tig = lane & 3;
    const int wm   = (wid >> 1) * 32;
    const int wn   = (wid & 1) * 64;
    const int nb   = blockIdx.x;          // 0..3 col block
    const int bm   = blockIdx.y * 128;

    const int srow = tid >> 1;            // staging row 0..127
    const int sseg = (tid & 1) * 16;      // halves offset 0 / 16

    if (tid < 128) {
        sb[0][tid] = g_bbase[nb * 128 + tid];
        sb[1][tid] = g_mb3[nb * 128 + tid];
        sb[2][tid] = g_mb3[512 + nb * 128 + tid];
        sb[3][tid] = g_mb3[1024 + nb * 128 + tid];
    }

    float acc[2][8][4];
#pragma unroll
    for (int a = 0; a < 2; a++)
#pragma unroll
        for (int b = 0; b < 8; b++)
#pragma unroll
            for (int q = 0; q < 4; q++) acc[a][b][q] = 0.f;

#define STAGE(BUF, C) do {                                                       \
    int k0 = (C) * 32;                                                           \
    int kk = k0 + sseg;                                                          \
    const float* srcp = (kk < 384) ? (g_S + (size_t)(bm + srow) * G3 + kk)       \
                                   : (x + (size_t)(bm + srow) * D + kk - 384);   \
    const float4* s4 = (const float4*)srcp;                                      \
    float4 f0 = s4[0], f1 = s4[1], f2 = s4[2], f3 = s4[3];                       \
    __half2* ad = (__half2*)&As[BUF][srow * ASTR + sseg];                        \
    ad[0] = __floats2half2_rn(f0.x, f0.y);                                       \
    ad[1] = __floats2half2_rn(f0.z, f0.w);                                       \
    ad[2] = __floats2half2_rn(f1.x, f1.y);                                       \
    ad[3] = __floats2half2_rn(f1.z, f1.w);                                       \
    ad[4] = __floats2half2_rn(f2.x, f2.y);                                       \
    ad[5] = __floats2half2_rn(f2.z, f2.w);                                       \
    ad[6] = __floats2half2_rn(f3.x, f3.y);                                       \
    ad[7] = __floats2half2_rn(f3.z, f3.w);                                       \
    const uint4* bsrc = (const uint4*)(g_Wh + (size_t)(nb * 128 + srow) * 512 + kk); \
    uint4* bdst = (uint4*)&Bs[BUF][srow * ASTR + sseg];                          \
    bdst[0] = bsrc[0];                                                           \
    bdst[1] = bsrc[1];                                                           \
} while (0)

    STAGE(0, 0);
    __syncthreads();

    const int NC = 16;
    for (int c = 0; c < NC; c++) {
        int b = c & 1;
        if (c + 1 < NC) STAGE(b ^ 1, c + 1);
        const uint32_t* Aw = (const uint32_t*)As[b];
        const uint32_t* Bw = (const uint32_t*)Bs[b];
#pragma unroll
        for (int s = 0; s < 2; s++) {
            unsigned a[2][4];
#pragma unroll
            for (int mt = 0; mt < 2; mt++) {
                int r0 = (wm + mt * 16 + gid) * (ASTR / 2) + s * 8 + tig;
                int r1 = (wm + mt * 16 + gid + 8) * (ASTR / 2) + s * 8 + tig;
                a[mt][0] = Aw[r0];
                a[mt][1] = Aw[r1];
                a[mt][2] = Aw[r0 + 4];
                a[mt][3] = Aw[r1 + 4];
            }
#pragma unroll
            for (int nt = 0; nt < 8; nt++) {
                int bi = (wn + nt * 8 + gid) * (ASTR / 2) + s * 8 + tig;
                unsigned b0 = Bw[bi];
                unsigned b1 = Bw[bi + 4];
                mma_f16(acc[0][nt], a[0], b0, b1);
                mma_f16(acc[1][nt], a[1], b0, b1);
            }
        }
        __syncthreads();
    }
#undef STAGE

    // GRU epilogue, fully register-local per output element
    const int h64 = wn >> 6;   // 0 or 1
#pragma unroll
    for (int mt = 0; mt < 2; mt++) {
#pragma unroll
        for (int rsel = 0; rsel < 2; rsel++) {
            int row = bm + wm + mt * 16 + gid + rsel * 8;
            float c0 = g_cnt[row * 4], c1 = g_cnt[row * 4 + 1], c2 = g_cnt[row * 4 + 2];
#pragma unroll
            for (int h = 0; h < 2; h++) {
                int jbase = nb * 32 + h64 * 16 + h * 8 + tig * 2;
                float2 o;
#pragma unroll
                for (int p = 0; p < 2; p++) {
                    int q = rsel * 2 + p;
                    int lR = wn + h * 8 + tig * 2 + p;
                    int lZ = lR + 16, lN = lR + 32, lH = lR + 48;
                    float vR = acc[mt][0 + h][q] + sb[0][lR]
                             + c0 * sb[1][lR] + c1 * sb[2][lR] + c2 * sb[3][lR];
                    float vZ = acc[mt][2 + h][q] + sb[0][lZ]
                             + c0 * sb[1][lZ] + c1 * sb[2][lZ] + c2 * sb[3][lZ];
                    float vN = acc[mt][4 + h][q] + sb[0][lN]
                             + c0 * sb[1][lN] + c1 * sb[2][lN] + c2 * sb[3][lN];
                    float vH = acc[mt][6 + h][q] + sb[0][lH];  // mb3 = 0 for h_n cols
                    float rg = sigm(vR), zg = sigm(vZ);
                    float ng = tanhf(vN + rg * vH);
                    float hp = x[(size_t)row * D + jbase + p];
                    (&o.x)[p] = (1.f - zg) * ng + zg * hp;
                }
                *(float2*)(xn + (size_t)row * D + jbase) = o;
            }
        }
    }
}

// ---------------- readout ----------------
__global__ void k_zero_pool() {
    int i = blockIdx.x * 256 + threadIdx.x;
    if (i < NG * D) g_pool[i] = 0.f;
    if (i < NG) g_pcnt[i] = 0.f;
}

__global__ void k_pool(const float* __restrict__ x, const int* __restrict__ batch) {
    int idx = blockIdx.x * 256 + threadIdx.x;
    if (idx >= NN * D) return;
    int n = idx >> 7, d = idx & 127;
    int g = batch[n];
    atomicAdd(&g_pool[g * D + d], x[idx]);
    if (d == 0) atomicAdd(&g_pcnt[g], 1.f);
}

__global__ void k_mlp(const float* __restrict__ W1, const float* __restrict__ b1,
                      const float* __restrict__ W2, const float* __restrict__ b2,
                      float* __restrict__ out) {
    int g = blockIdx.x;
    int d = threadIdx.x;
    __shared__ float ps[128];
    __shared__ float red[4];
    float c = g_pcnt[g]; if (c < 1.f) c = 1.f;
    ps[d] = g_pool[g * D + d] / c;
    __syncthreads();
    float acc = b1[d];
#pragma unroll
    for (int k = 0; k < 128; k++) acc += ps[k] * W1[d * 128 + k];
    float h = acc > 0.f ? acc : 0.f;
    float v = h * W2[d];
#pragma unroll
    for (int off = 16; off; off >>= 1) v += __shfl_down_sync(0xffffffff, v, off);
    if ((d & 31) == 0) red[d >> 5] = v;
    __syncthreads();
    if (d == 0) out[g] = red[0] + red[1] + red[2] + red[3] + b2[0];
}

// ---------------- launch ----------------
extern "C" void kernel_launch(void* const* d_in, const int* in_sizes, int n_in,
                              void* d_out, int out_size) {
    const int*   x_type   = (const int*)d_in[0];
    const int*   x_tok    = (const int*)d_in[1];
    const float* x_small  = (const float*)d_in[2];
    const int*   ei       = (const int*)d_in[3];
    const int*   etype    = (const int*)d_in[4];
    const int*   batch    = (const int*)d_in[5];
    const float* type_emb = (const float*)d_in[6];
    const float* tok_emb  = (const float*)d_in[7];
    const float* msg_W    = (const float*)d_in[8];
    const float* msg_b    = (const float*)d_in[9];
    const float* W_ih     = (const float*)d_in[10];
    const float* W_hh     = (const float*)d_in[11];
    const float* b_ih     = (const float*)d_in[12];
    const float* b_hh     = (const float*)d_in[13];
    const float* pW1      = (const float*)d_in[14];
    const float* pb1      = (const float*)d_in[15];
    const float* pW2      = (const float*)d_in[16];
    const float* pb2      = (const float*)d_in[17];

    const int E = NE;
    const int* src = ei;
    const int* dst = ei + E;

    float *pX0, *pX1;
    cudaGetSymbolAddress((void**)&pX0, g_x0);
    cudaGetSymbolAddress((void**)&pX1, g_x1);

    // preprocessing
    k_prep_wc<<<(384 * 128 + 255) / 256, 256>>>(msg_W);
    k_prep_comb<<<(384 * 384 + 255) / 256, 256>>>(W_ih);
    k_prep_wh<<<(512 * 512 + 255) / 256, 256>>>(W_hh);
    k_prep_bias<<<(2048 + 255) / 256, 256>>>(b_ih, b_hh, msg_b, W_ih);
    k_init<<<(NN * D + 255) / 256, 256>>>(x_type, x_tok, x_small, type_emb, tok_emb);
    k_zero_hist<<<(NN + 255) / 256, 256>>>();
    k_hist<<<(E + 255) / 256, 256>>>(dst, E);
    k_scan1<<<98, 1024>>>();
    k_scan2<<<1, 1>>>(98);
    k_scan3<<<98, 1024>>>();
    k_copycur<<<(NN + 255) / 256, 256>>>();
    k_scatter<<<(E + 255) / 256, 256>>>(src, dst, etype, E);

    float* cur = pX0;
    float* nxt = pX1;
    dim3 gBig(4, MPAD / 128);
    for (int it = 0; it < 8; it++) {
        k_gather<<<(NN + 7) / 8, 256>>>(cur);
        k_big<<<gBig, 256>>>(cur, nxt);
        float* t = cur; cur = nxt; nxt = t;
    }

    k_zero_pool<<<33, 256>>>();
    k_pool<<<(NN * D + 255) / 256, 256>>>(cur, batch);
    k_mlp<<<NG, 128>>>(pW1, pb1, pW2, pb2, (float*)d_out);
}